// round 16
// baseline (speedup 1.0000x reference)
#include <cuda_runtime.h>
#include <math.h>

// Problem constants
#define NP     2048     // particles
#define NR     128      // rays
#define NS     256      // ray steps
#define MAPW   1024
#define MAPH   1024
#define ND     256      // sensor table dim
#define OCC_THRESH 0.97f

// Map window that can ever be sampled (particles ~N(512,20^2) +-3.6 sigma,
// rays reach <=256.5):  y in [176, 848), x in [160, 864).
#define WINY0   176
#define WROWS   672
#define WINXW0  5            // first x bitmap word (x = 160)
#define WWORDS  22           // x words per row (covers x in [160,864))
#define WT      (WROWS * WWORDS)      // 14784 compact window words
#define WPAD    23           // padded smem row stride (odd -> conflict-free)
#define WIN_U32 (WROWS * WPAD)

#define PPB 8                // particles per block
#define TPB (PPB * 128)      // 1024 threads
#define GRID (NP / PPB)      // 256 blocks -> one wave, 2 blocks/SM, 64 warps/SM

// Scratch (no cudaMalloc allowed)
__device__ float    g_pred[NP * 3];     // predicted particles
__device__ float    g_trig[NP * 2];     // sin(th), cos(th)
__device__ float    g_logl[NP];         // per-particle log likelihood
__device__ float    g_logits[NP];       // log_weights + log_l
__device__ float    g_cum[NP];          // normalized-weight cumsum
__device__ __align__(16) unsigned g_win[WT];   // compact window occupancy bits
__device__ int      g_perm[NR];         // rays sorted by angle

// ---------------------------------------------------------------------------
// Setup (R9 verbatim): blocks 0..461 build the COMPACT WINDOW bitmap (8
// threads per word, float4 loads, ballot-OR packing); block 462 sorts rays.
// ---------------------------------------------------------------------------
__global__ __launch_bounds__(256) void kernSetup(
    const float* __restrict__ map_grid,
    const float* __restrict__ obs_angles)
{
    if (blockIdx.x < (WT * 8) / 256) {                    // 462 blocks
        const int gid = blockIdx.x * 256 + threadIdx.x;   // 0 .. 118271
        const int w   = gid >> 3;                         // window word
        const int sub = gid & 7;                          // float4 within word
        const int row = w / WWORDS;
        const int cw  = w - row * WWORDS;
        const int cell = (row + WINY0) * MAPW + (WINXW0 * 32) + cw * 32 + sub * 4;
        const float4 v = __ldg((const float4*)(map_grid + cell));
        unsigned b = (v.x > OCC_THRESH ? 1u : 0u)
                   | (v.y > OCC_THRESH ? 2u : 0u)
                   | (v.z > OCC_THRESH ? 4u : 0u)
                   | (v.w > OCC_THRESH ? 8u : 0u);
        const int lane = threadIdx.x & 31;
        const int grp  = lane >> 3;                       // 8-lane group = 1 word
        const unsigned gmask = 0xFFu << (grp * 8);
        unsigned word = __reduce_or_sync(gmask, b << (sub * 4));
        if (sub == 0) g_win[w] = word;
    } else {
        __shared__ float s_a[NR];
        const int i = threadIdx.x;
        if (i < NR) s_a[i] = obs_angles[i];
        __syncthreads();
        if (i < NR) {
            const float a = s_a[i];
            int rank = 0;
            #pragma unroll 8
            for (int j = 0; j < NR; j++) {
                float b = s_a[j];
                rank += (b < a) || (b == a && j < i);
            }
            g_perm[rank] = i;
        }
    }
}

// ---------------------------------------------------------------------------
// Kernel A (R15 verbatim, IDEMPOTENT — launched twice this round to measure
// its true marginal cost): 8 particles/block, warp-ballot march on the smem
// window bitmap.  Per-ray values by ORIGINAL ray index; exact R1 reduction.
// ---------------------------------------------------------------------------
__global__ __launch_bounds__(TPB, 2) void kernA(
    const float* __restrict__ particles,
    const float* __restrict__ log_weights,
    const float* __restrict__ obs_angles,
    const float* __restrict__ obs_dists,
    const float* __restrict__ map_grid,
    const float* __restrict__ sensor_table,
    const float* __restrict__ twist,
    const float* __restrict__ motion_noise)
{
    extern __shared__ unsigned smw[];
    unsigned* sm_bm  = smw;                               // WROWS*WPAD u32
    float*    s_val  = (float*)(smw + WIN_U32);           // PPB*128 floats
    float*    s_part = s_val + PPB * 128;                 // PPB*4 floats

    const int tid = threadIdx.x;

    // ---- copy compact window bitmap into padded smem rows (coalesced) ----
    for (int i = tid; i < WT; i += TPB) {
        int row = i / WWORDS;
        int j   = i - row * WWORDS;
        sm_bm[row * WPAD + j] = __ldg(&g_win[i]);
    }

    const int pi   = tid >> 7;        // particle within block (0..7)
    const int r    = tid & 127;       // sorted-rank ray slot
    const int lane = tid & 31;
    const int p    = blockIdx.x * PPB + pi;   // always < NP (GRID*PPB == NP)

    float x, y, th, c, s;
    int ray;
    bool my_inw;
    {
        ray = g_perm[r];
        // Motion update (mul then add, no FMA contraction)
        x  = __fadd_rn(__fadd_rn(particles[p*3+0], twist[0]),
                       __fmul_rn(motion_noise[p*3+0], 0.5f));
        y  = __fadd_rn(__fadd_rn(particles[p*3+1], twist[1]),
                       __fmul_rn(motion_noise[p*3+1], 0.5f));
        th = __fadd_rn(__fadd_rn(particles[p*3+2], twist[2]),
                       __fmul_rn(motion_noise[p*3+2], 0.02f));
        if (r < 3) g_pred[p*3 + r] = (r == 0) ? x : ((r == 1) ? y : th);
        if (r == 3) g_trig[p*2 + 0] = sinf(th);
        if (r == 4) g_trig[p*2 + 1] = cosf(th);

        const float ang = __fadd_rn(th, obs_angles[ray]);
        c = cosf(ang);
        s = sinf(ang);

        // In-window test for this ray's whole segment (t in [1,256], convex)
        float ex0 = __fadd_rn(x, c), ex1 = __fadd_rn(x, __fmul_rn(256.f, c));
        float ey0 = __fadd_rn(y, s), ey1 = __fadd_rn(y, __fmul_rn(256.f, s));
        float xmn = fminf(ex0, ex1), xmx = fmaxf(ex0, ex1);
        float ymn = fminf(ey0, ey1), ymx = fmaxf(ey0, ey1);
        my_inw = (xmn >= 162.f) && (xmx < 862.f) &&
                 (ymn >= (float)(WINY0 + 2)) && (ymx < (float)(WINY0 + WROWS - 2));
    }

    __syncthreads();   // smem bitmap ready

    int my_ebin = 255;   // no-hit: dist=256 -> clip(int(256),0,255)=255
    {
        const unsigned inw_mask = __ballot_sync(0xffffffffu, my_inw);
        const float lanef = (float)(lane + 1);

        #pragma unroll 1
        for (int rr = 0; rr < 32; rr++) {
            const float rc = __shfl_sync(0xffffffffu, c, rr);
            const float rs = __shfl_sync(0xffffffffu, s, rr);
            int ebin = 255;
            if ((inw_mask >> rr) & 1u) {
                // Fast path: padded smem window, no clamping needed.
                float tf = lanef;
                #pragma unroll 1
                for (int it = 0; it < 8; it++) {
                    float px = __fadd_rn(x, __fmul_rn(tf, rc));
                    float py = __fadd_rn(y, __fmul_rn(tf, rs));
                    int ix = __float2int_rz(px);
                    int iy = __float2int_rz(py);
                    unsigned w = sm_bm[(iy - WINY0) * WPAD + ((ix >> 5) - WINXW0)];
                    unsigned m = __ballot_sync(0xffffffffu, (w >> (ix & 31)) & 1u);
                    if (m) { ebin = min(it * 32 + __ffs(m), 255); break; }
                    tf = __fadd_rn(tf, 32.0f);
                }
            } else {
                // Fallback: read the map directly with full clamping (same
                // boolean as the bitmap bit; outliers only, never taken here).
                float tf = lanef;
                #pragma unroll 1
                for (int it = 0; it < 8; it++) {
                    float px = __fadd_rn(x, __fmul_rn(tf, rc));
                    float py = __fadd_rn(y, __fmul_rn(tf, rs));
                    int ix = min(max(__float2int_rz(px), 0), MAPW - 1);
                    int iy = min(max(__float2int_rz(py), 0), MAPH - 1);
                    bool occ = __ldg(&map_grid[iy * MAPW + ix]) > OCC_THRESH;
                    unsigned m = __ballot_sync(0xffffffffu, occ);
                    if (m) { ebin = min(it * 32 + __ffs(m), 255); break; }
                    tf = __fadd_rn(tf, 32.0f);
                }
            }
            my_ebin = (lane == rr) ? ebin : my_ebin;
        }

        // bin_w = 1.0 exactly: o_bin = clip(int(obs_dist),0,255)
        int ob = min(max(__float2int_rz(obs_dists[ray]), 0), ND - 1);
        float val = __ldg(&sensor_table[my_ebin * ND + ob]);
        s_val[pi * 128 + ray] = val;          // store by ORIGINAL ray index
    }
    __syncthreads();

    // Reduce in the exact round-1 order: thread slot r <- ray r.
    {
        float v = s_val[pi * 128 + r];
        #pragma unroll
        for (int o = 16; o > 0; o >>= 1)
            v += __shfl_down_sync(0xffffffffu, v, o);
        if ((r & 31) == 0) s_part[pi * 4 + (r >> 5)] = v;
    }
    __syncthreads();
    if (r == 0) {
        float ll = ((s_part[pi*4+0] + s_part[pi*4+1]) + s_part[pi*4+2]) + s_part[pi*4+3];
        g_logl[p] = ll;
        g_logits[p] = __fadd_rn(log_weights[p], __fmul_rn(1.0f, ll));
    }
}

// ---------------------------------------------------------------------------
// Kernel B1 (R9 verbatim): max + 7 fused reductions + ping-pong scan.
// ---------------------------------------------------------------------------
__global__ __launch_bounds__(1024) void kernB1(float* __restrict__ out)
{
    __shared__ float s_buf0[NP];
    __shared__ float s_buf1[NP];
    __shared__ float s_red[7 * 32];
    __shared__ float s_tot[8];

    const int tid  = threadIdx.x;
    const int lane = tid & 31;
    const int wrp  = tid >> 5;
    const int i0 = tid, i1 = tid + 1024;

    float l0 = g_logits[i0];
    float l1 = g_logits[i1];
    {
        float v = fmaxf(l0, l1);
        #pragma unroll
        for (int o = 16; o > 0; o >>= 1)
            v = fmaxf(v, __shfl_down_sync(0xffffffffu, v, o));
        if (lane == 0) s_red[wrp] = v;
        __syncthreads();
        if (wrp == 0) {
            float m2 = s_red[lane];
            #pragma unroll
            for (int o = 16; o > 0; o >>= 1)
                m2 = fmaxf(m2, __shfl_down_sync(0xffffffffu, m2, o));
            if (lane == 0) s_tot[7] = m2;
        }
        __syncthreads();
    }
    const float mx   = s_tot[7];
    const float mx10 = __fmul_rn(mx, 10.0f);

    float acc[7] = {0.f, 0.f, 0.f, 0.f, 0.f, 0.f, 0.f};
    #pragma unroll
    for (int k = 0; k < 2; k++) {
        int i = (k == 0) ? i0 : i1;
        float l = (k == 0) ? l0 : l1;
        float e10 = expf(__fsub_rn(__fmul_rn(l, 10.0f), mx10));
        float e1  = expf(__fsub_rn(l, mx));
        float px = g_pred[i*3+0];
        float py = g_pred[i*3+1];
        acc[0] += e10;
        acc[1] += e10 * px;
        acc[2] += e10 * py;
        acc[3] += e10 * g_trig[i*2+0];
        acc[4] += e10 * g_trig[i*2+1];
        acc[5] += e1;
        acc[6] += e1 * g_logl[i];
        s_buf0[i] = e1;
    }
    #pragma unroll
    for (int q = 0; q < 7; q++) {
        float v = acc[q];
        #pragma unroll
        for (int o = 16; o > 0; o >>= 1)
            v += __shfl_down_sync(0xffffffffu, v, o);
        if (lane == 0) s_red[q * 32 + wrp] = v;
    }
    __syncthreads();
    if (wrp == 0) {
        #pragma unroll
        for (int q = 0; q < 7; q++) {
            float v = s_red[q * 32 + lane];
            #pragma unroll
            for (int o = 16; o > 0; o >>= 1)
                v += __shfl_down_sync(0xffffffffu, v, o);
            if (lane == 0) s_tot[q] = v;
        }
    }
    __syncthreads();
    const float S1 = s_tot[5];

    s_buf0[i0] = s_buf0[i0] / S1;
    s_buf0[i1] = s_buf0[i1] / S1;
    __syncthreads();

    float* src = s_buf0;
    float* dst = s_buf1;
    for (int stride = 1; stride < NP; stride <<= 1) {
        float a0 = src[i0] + ((i0 >= stride) ? src[i0 - stride] : 0.f);
        float a1 = src[i1] + ((i1 >= stride) ? src[i1 - stride] : 0.f);
        dst[i0] = (i0 >= stride) ? a0 : src[i0];
        dst[i1] = (i1 >= stride) ? a1 : src[i1];
        __syncthreads();
        float* tmp = src; src = dst; dst = tmp;
    }
    g_cum[i0] = src[i0];
    g_cum[i1] = src[i1];

    if (tid == 0) {
        const float S10 = s_tot[0];
        out[0] = s_tot[1] / S10;
        out[1] = s_tot[2] / S10;
        out[2] = atan2f(s_tot[3] / S10, s_tot[4] / S10);
        out[3 + NP * 3] = s_tot[6] / S1;   // confidence, last element
    }
}

// ---------------------------------------------------------------------------
// Kernel B2 (R9 verbatim): 8 blocks x 256, resampling + gather + noise.
// ---------------------------------------------------------------------------
__global__ __launch_bounds__(256) void kernB2(
    const float* __restrict__ noise_after,
    const float* __restrict__ resample_u,
    float* __restrict__ out)
{
    __shared__ float s_cum[NP];
    const int tid = threadIdx.x;
    #pragma unroll
    for (int k = 0; k < NP / 256; k++)
        s_cum[k * 256 + tid] = g_cum[k * 256 + tid];
    __syncthreads();

    const int i = blockIdx.x * 256 + tid;
    const float u = resample_u[0];
    float pos = __fdiv_rn(__fadd_rn((float)i, u), (float)NP);
    int lo = 0, hi = NP;
    while (lo < hi) {
        int mid = (lo + hi) >> 1;
        if (s_cum[mid] < pos) lo = mid + 1;
        else hi = mid;
    }
    int idx = min(lo, NP - 1);
    out[3 + i*3 + 0] = __fadd_rn(g_pred[idx*3+0], __fmul_rn(noise_after[i*3+0], 0.2f));
    out[3 + i*3 + 1] = __fadd_rn(g_pred[idx*3+1], __fmul_rn(noise_after[i*3+1], 0.2f));
    out[3 + i*3 + 2] = __fadd_rn(g_pred[idx*3+2], __fmul_rn(noise_after[i*3+2], 0.01f));
}

// ---------------------------------------------------------------------------
// Launch — MEASUREMENT ROUND: kernA launched TWICE (idempotent, bit-identical
// output).  dur_us - 37.35 = kernA's true marginal cost; this calibrates the
// budget for the next optimization round.
// ---------------------------------------------------------------------------
extern "C" void kernel_launch(void* const* d_in, const int* in_sizes, int n_in,
                              void* d_out, int out_size)
{
    const float* particles    = (const float*)d_in[0];
    const float* log_weights  = (const float*)d_in[1];
    const float* obs_angles   = (const float*)d_in[2];
    const float* obs_dists    = (const float*)d_in[3];
    const float* map_grid     = (const float*)d_in[4];
    const float* sensor_table = (const float*)d_in[5];
    const float* twist        = (const float*)d_in[6];
    const float* motion_noise = (const float*)d_in[7];
    const float* resample_u   = (const float*)d_in[8];
    const float* noise_after  = (const float*)d_in[9];
    float* out = (float*)d_out;

    // Dynamic smem: padded bitmap window + per-ray values + partials
    const int smemA = WIN_U32 * 4 + PPB * 128 * 4 + PPB * 4 * 4;   // ~66.0 KB
    cudaFuncSetAttribute(kernA, cudaFuncAttributeMaxDynamicSharedMemorySize, smemA);

    kernSetup<<<(WT * 8) / 256 + 1, 256>>>(map_grid, obs_angles);
    kernA<<<GRID, TPB, smemA>>>(particles, log_weights, obs_angles, obs_dists,
                                map_grid, sensor_table, twist, motion_noise);
    kernA<<<GRID, TPB, smemA>>>(particles, log_weights, obs_angles, obs_dists,
                                map_grid, sensor_table, twist, motion_noise);
    kernB1<<<1, 1024>>>(out);
    kernB2<<<NP / 256, 256>>>(noise_after, resample_u, out);
}

// round 17
// speedup vs baseline: 1.7899x; 1.7899x over previous
#include <cuda_runtime.h>
#include <math.h>

// Problem constants
#define NP     2048     // particles
#define NR     128      // rays
#define NS     256      // ray steps
#define MAPW   1024
#define MAPH   1024
#define ND     256      // sensor table dim
#define OCC_THRESH 0.97f

// Map window that can ever be sampled (particles ~N(512,20^2) +-3.6 sigma,
// rays reach <=256.5):  y in [176, 848), x in [160, 864).
#define WINY0   176
#define WROWS   672
#define WINXW0  5            // first x bitmap word (x = 160)
#define WWORDS  22           // x words per row (covers x in [160,864))
#define WT      (WROWS * WWORDS)      // 14784 compact window words
#define WPAD    23           // padded smem row stride (odd -> conflict-free)
#define WIN_U32 (WROWS * WPAD)

#define PPB 7                // particles per block
#define TPB (PPB * 128)      // 896 threads -> 36-reg budget at 2 blocks/SM
#define GRID ((NP + PPB - 1) / PPB)   // 293

// Scratch (no cudaMalloc allowed)
__device__ float    g_pred[NP * 3];     // predicted particles
__device__ float    g_trig[NP * 2];     // sin(th), cos(th)
__device__ float    g_logl[NP];         // per-particle log likelihood
__device__ float    g_logits[NP];       // log_weights + log_l
__device__ float    g_cum[NP];          // normalized-weight cumsum
__device__ __align__(16) unsigned g_win[WT];   // compact window occupancy bits
__device__ int      g_perm[NR];         // rays sorted by angle

// ---------------------------------------------------------------------------
// Setup (R9 verbatim): blocks 0..461 build the COMPACT WINDOW bitmap (8
// threads per word, float4 loads, ballot-OR packing); block 462 sorts rays.
// ---------------------------------------------------------------------------
__global__ __launch_bounds__(256) void kernSetup(
    const float* __restrict__ map_grid,
    const float* __restrict__ obs_angles)
{
    if (blockIdx.x < (WT * 8) / 256) {                    // 462 blocks
        const int gid = blockIdx.x * 256 + threadIdx.x;   // 0 .. 118271
        const int w   = gid >> 3;                         // window word
        const int sub = gid & 7;                          // float4 within word
        const int row = w / WWORDS;
        const int cw  = w - row * WWORDS;
        const int cell = (row + WINY0) * MAPW + (WINXW0 * 32) + cw * 32 + sub * 4;
        const float4 v = __ldg((const float4*)(map_grid + cell));
        unsigned b = (v.x > OCC_THRESH ? 1u : 0u)
                   | (v.y > OCC_THRESH ? 2u : 0u)
                   | (v.z > OCC_THRESH ? 4u : 0u)
                   | (v.w > OCC_THRESH ? 8u : 0u);
        const int lane = threadIdx.x & 31;
        const int grp  = lane >> 3;                       // 8-lane group = 1 word
        const unsigned gmask = 0xFFu << (grp * 8);
        unsigned word = __reduce_or_sync(gmask, b << (sub * 4));
        if (sub == 0) g_win[w] = word;
    } else {
        __shared__ float s_a[NR];
        const int i = threadIdx.x;
        if (i < NR) s_a[i] = obs_angles[i];
        __syncthreads();
        if (i < NR) {
            const float a = s_a[i];
            int rank = 0;
            #pragma unroll 8
            for (int j = 0; j < NR; j++) {
                float b = s_a[j];
                rank += (b < a) || (b == a && j < i);
            }
            g_perm[rank] = i;
        }
    }
}

// ---------------------------------------------------------------------------
// Kernel A: 7 particles/block, warp-ballot march.  INNER LOOP FULLY UNROLLED
// (no counter/branch overhead), warp-uniform in-window hoist, base-pointer
// folded addressing.  Probe sequence and all FP ops identical to R9/R15.
// Per-ray values stored by ORIGINAL ray index; reduction in exact R1 order.
// ---------------------------------------------------------------------------
__global__ __launch_bounds__(TPB, 2) void kernA(
    const float* __restrict__ particles,
    const float* __restrict__ log_weights,
    const float* __restrict__ obs_angles,
    const float* __restrict__ obs_dists,
    const float* __restrict__ map_grid,
    const float* __restrict__ sensor_table,
    const float* __restrict__ twist,
    const float* __restrict__ motion_noise)
{
    extern __shared__ unsigned smw[];
    unsigned* sm_bm  = smw;                               // WROWS*WPAD u32
    float*    s_val  = (float*)(smw + WIN_U32);           // PPB*128 floats
    float*    s_part = s_val + PPB * 128;                 // PPB*4 floats

    const int tid = threadIdx.x;

    // ---- copy compact window bitmap into padded smem rows (coalesced) ----
    for (int i = tid; i < WT; i += TPB) {
        int row = i / WWORDS;
        int j   = i - row * WWORDS;
        sm_bm[row * WPAD + j] = __ldg(&g_win[i]);
    }
    // Base pointer with window offset folded in: index = iy*WPAD + (ix>>5).
    const unsigned* bm0 = sm_bm - (WINY0 * WPAD + WINXW0);

    const int pi   = tid >> 7;        // particle within block
    const int r    = tid & 127;       // sorted-rank ray slot
    const int lane = tid & 31;
    const int p    = blockIdx.x * PPB + pi;
    const bool active = (p < NP);     // uniform per warp

    float x = 0.f, y = 0.f, th = 0.f, c = 0.f, s = 0.f;
    int ray = 0;
    bool my_inw = false;
    if (active) {
        ray = g_perm[r];
        // Motion update (mul then add, no FMA contraction)
        x  = __fadd_rn(__fadd_rn(particles[p*3+0], twist[0]),
                       __fmul_rn(motion_noise[p*3+0], 0.5f));
        y  = __fadd_rn(__fadd_rn(particles[p*3+1], twist[1]),
                       __fmul_rn(motion_noise[p*3+1], 0.5f));
        th = __fadd_rn(__fadd_rn(particles[p*3+2], twist[2]),
                       __fmul_rn(motion_noise[p*3+2], 0.02f));
        if (r < 3) g_pred[p*3 + r] = (r == 0) ? x : ((r == 1) ? y : th);
        if (r == 3) g_trig[p*2 + 0] = sinf(th);
        if (r == 4) g_trig[p*2 + 1] = cosf(th);

        const float ang = __fadd_rn(th, obs_angles[ray]);
        c = cosf(ang);
        s = sinf(ang);

        // In-window test for this ray's whole segment (t in [1,256], convex)
        float ex0 = __fadd_rn(x, c), ex1 = __fadd_rn(x, __fmul_rn(256.f, c));
        float ey0 = __fadd_rn(y, s), ey1 = __fadd_rn(y, __fmul_rn(256.f, s));
        float xmn = fminf(ex0, ex1), xmx = fmaxf(ex0, ex1);
        float ymn = fminf(ey0, ey1), ymx = fmaxf(ey0, ey1);
        my_inw = (xmn >= 162.f) && (xmx < 862.f) &&
                 (ymn >= (float)(WINY0 + 2)) && (ymx < (float)(WINY0 + WROWS - 2));
    }

    __syncthreads();   // smem bitmap ready

    int my_ebin = 255;   // no-hit: dist=256 -> clip(int(256),0,255)=255
    if (active) {
        const unsigned inw_mask = __ballot_sync(0xffffffffu, my_inw);
        const float lanef = (float)(lane + 1);

        if (inw_mask == 0xffffffffu) {
            // Clean path: all 32 rays in-window (always true for this input).
            #pragma unroll 1
            for (int rr = 0; rr < 32; rr++) {
                const float rc = __shfl_sync(0xffffffffu, c, rr);
                const float rs = __shfl_sync(0xffffffffu, s, rr);
                int ebin = 255;
                float tf = lanef;
                #pragma unroll
                for (int it = 0; it < 8; it++) {
                    float px = __fadd_rn(x, __fmul_rn(tf, rc));
                    float py = __fadd_rn(y, __fmul_rn(tf, rs));
                    int ix = __float2int_rz(px);
                    int iy = __float2int_rz(py);
                    unsigned w = bm0[iy * WPAD + (ix >> 5)];
                    unsigned m = __ballot_sync(0xffffffffu, (w >> (ix & 31)) & 1u);
                    if (m) { ebin = min(it * 32 + __ffs(m), 255); break; }
                    tf = __fadd_rn(tf, 32.0f);
                }
                my_ebin = (lane == rr) ? ebin : my_ebin;
            }
        } else {
            // General path (outliers): per-ray window test + clamped fallback.
            #pragma unroll 1
            for (int rr = 0; rr < 32; rr++) {
                const float rc = __shfl_sync(0xffffffffu, c, rr);
                const float rs = __shfl_sync(0xffffffffu, s, rr);
                int ebin = 255;
                if ((inw_mask >> rr) & 1u) {
                    float tf = lanef;
                    #pragma unroll 1
                    for (int it = 0; it < 8; it++) {
                        float px = __fadd_rn(x, __fmul_rn(tf, rc));
                        float py = __fadd_rn(y, __fmul_rn(tf, rs));
                        int ix = __float2int_rz(px);
                        int iy = __float2int_rz(py);
                        unsigned w = bm0[iy * WPAD + (ix >> 5)];
                        unsigned m = __ballot_sync(0xffffffffu, (w >> (ix & 31)) & 1u);
                        if (m) { ebin = min(it * 32 + __ffs(m), 255); break; }
                        tf = __fadd_rn(tf, 32.0f);
                    }
                } else {
                    float tf = lanef;
                    #pragma unroll 1
                    for (int it = 0; it < 8; it++) {
                        float px = __fadd_rn(x, __fmul_rn(tf, rc));
                        float py = __fadd_rn(y, __fmul_rn(tf, rs));
                        int ix = min(max(__float2int_rz(px), 0), MAPW - 1);
                        int iy = min(max(__float2int_rz(py), 0), MAPH - 1);
                        bool occ = __ldg(&map_grid[iy * MAPW + ix]) > OCC_THRESH;
                        unsigned m = __ballot_sync(0xffffffffu, occ);
                        if (m) { ebin = min(it * 32 + __ffs(m), 255); break; }
                        tf = __fadd_rn(tf, 32.0f);
                    }
                }
                my_ebin = (lane == rr) ? ebin : my_ebin;
            }
        }

        // bin_w = 1.0 exactly: o_bin = clip(int(obs_dist),0,255)
        int ob = min(max(__float2int_rz(obs_dists[ray]), 0), ND - 1);
        float val = __ldg(&sensor_table[my_ebin * ND + ob]);
        s_val[pi * 128 + ray] = val;          // store by ORIGINAL ray index
    }
    __syncthreads();

    // Reduce in the exact round-1 order: thread slot r <- ray r.
    if (active) {
        float v = s_val[pi * 128 + r];
        #pragma unroll
        for (int o = 16; o > 0; o >>= 1)
            v += __shfl_down_sync(0xffffffffu, v, o);
        if ((r & 31) == 0) s_part[pi * 4 + (r >> 5)] = v;
    }
    __syncthreads();
    if (active && r == 0) {
        float ll = ((s_part[pi*4+0] + s_part[pi*4+1]) + s_part[pi*4+2]) + s_part[pi*4+3];
        g_logl[p] = ll;
        g_logits[p] = __fadd_rn(log_weights[p], __fmul_rn(1.0f, ll));
    }
}

// ---------------------------------------------------------------------------
// Kernel B1 (R9 verbatim): max + 7 fused reductions + ping-pong scan.
// ---------------------------------------------------------------------------
__global__ __launch_bounds__(1024) void kernB1(float* __restrict__ out)
{
    __shared__ float s_buf0[NP];
    __shared__ float s_buf1[NP];
    __shared__ float s_red[7 * 32];
    __shared__ float s_tot[8];

    const int tid  = threadIdx.x;
    const int lane = tid & 31;
    const int wrp  = tid >> 5;
    const int i0 = tid, i1 = tid + 1024;

    float l0 = g_logits[i0];
    float l1 = g_logits[i1];
    {
        float v = fmaxf(l0, l1);
        #pragma unroll
        for (int o = 16; o > 0; o >>= 1)
            v = fmaxf(v, __shfl_down_sync(0xffffffffu, v, o));
        if (lane == 0) s_red[wrp] = v;
        __syncthreads();
        if (wrp == 0) {
            float m2 = s_red[lane];
            #pragma unroll
            for (int o = 16; o > 0; o >>= 1)
                m2 = fmaxf(m2, __shfl_down_sync(0xffffffffu, m2, o));
            if (lane == 0) s_tot[7] = m2;
        }
        __syncthreads();
    }
    const float mx   = s_tot[7];
    const float mx10 = __fmul_rn(mx, 10.0f);

    float acc[7] = {0.f, 0.f, 0.f, 0.f, 0.f, 0.f, 0.f};
    #pragma unroll
    for (int k = 0; k < 2; k++) {
        int i = (k == 0) ? i0 : i1;
        float l = (k == 0) ? l0 : l1;
        float e10 = expf(__fsub_rn(__fmul_rn(l, 10.0f), mx10));
        float e1  = expf(__fsub_rn(l, mx));
        float px = g_pred[i*3+0];
        float py = g_pred[i*3+1];
        acc[0] += e10;
        acc[1] += e10 * px;
        acc[2] += e10 * py;
        acc[3] += e10 * g_trig[i*2+0];
        acc[4] += e10 * g_trig[i*2+1];
        acc[5] += e1;
        acc[6] += e1 * g_logl[i];
        s_buf0[i] = e1;
    }
    #pragma unroll
    for (int q = 0; q < 7; q++) {
        float v = acc[q];
        #pragma unroll
        for (int o = 16; o > 0; o >>= 1)
            v += __shfl_down_sync(0xffffffffu, v, o);
        if (lane == 0) s_red[q * 32 + wrp] = v;
    }
    __syncthreads();
    if (wrp == 0) {
        #pragma unroll
        for (int q = 0; q < 7; q++) {
            float v = s_red[q * 32 + lane];
            #pragma unroll
            for (int o = 16; o > 0; o >>= 1)
                v += __shfl_down_sync(0xffffffffu, v, o);
            if (lane == 0) s_tot[q] = v;
        }
    }
    __syncthreads();
    const float S1 = s_tot[5];

    s_buf0[i0] = s_buf0[i0] / S1;
    s_buf0[i1] = s_buf0[i1] / S1;
    __syncthreads();

    float* src = s_buf0;
    float* dst = s_buf1;
    for (int stride = 1; stride < NP; stride <<= 1) {
        float a0 = src[i0] + ((i0 >= stride) ? src[i0 - stride] : 0.f);
        float a1 = src[i1] + ((i1 >= stride) ? src[i1 - stride] : 0.f);
        dst[i0] = (i0 >= stride) ? a0 : src[i0];
        dst[i1] = (i1 >= stride) ? a1 : src[i1];
        __syncthreads();
        float* tmp = src; src = dst; dst = tmp;
    }
    g_cum[i0] = src[i0];
    g_cum[i1] = src[i1];

    if (tid == 0) {
        const float S10 = s_tot[0];
        out[0] = s_tot[1] / S10;
        out[1] = s_tot[2] / S10;
        out[2] = atan2f(s_tot[3] / S10, s_tot[4] / S10);
        out[3 + NP * 3] = s_tot[6] / S1;   // confidence, last element
    }
}

// ---------------------------------------------------------------------------
// Kernel B2 (R9 verbatim): 8 blocks x 256, resampling + gather + noise.
// ---------------------------------------------------------------------------
__global__ __launch_bounds__(256) void kernB2(
    const float* __restrict__ noise_after,
    const float* __restrict__ resample_u,
    float* __restrict__ out)
{
    __shared__ float s_cum[NP];
    const int tid = threadIdx.x;
    #pragma unroll
    for (int k = 0; k < NP / 256; k++)
        s_cum[k * 256 + tid] = g_cum[k * 256 + tid];
    __syncthreads();

    const int i = blockIdx.x * 256 + tid;
    const float u = resample_u[0];
    float pos = __fdiv_rn(__fadd_rn((float)i, u), (float)NP);
    int lo = 0, hi = NP;
    while (lo < hi) {
        int mid = (lo + hi) >> 1;
        if (s_cum[mid] < pos) lo = mid + 1;
        else hi = mid;
    }
    int idx = min(lo, NP - 1);
    out[3 + i*3 + 0] = __fadd_rn(g_pred[idx*3+0], __fmul_rn(noise_after[i*3+0], 0.2f));
    out[3 + i*3 + 1] = __fadd_rn(g_pred[idx*3+1], __fmul_rn(noise_after[i*3+1], 0.2f));
    out[3 + i*3 + 2] = __fadd_rn(g_pred[idx*3+2], __fmul_rn(noise_after[i*3+2], 0.01f));
}

// ---------------------------------------------------------------------------
// Launch
// ---------------------------------------------------------------------------
extern "C" void kernel_launch(void* const* d_in, const int* in_sizes, int n_in,
                              void* d_out, int out_size)
{
    const float* particles    = (const float*)d_in[0];
    const float* log_weights  = (const float*)d_in[1];
    const float* obs_angles   = (const float*)d_in[2];
    const float* obs_dists    = (const float*)d_in[3];
    const float* map_grid     = (const float*)d_in[4];
    const float* sensor_table = (const float*)d_in[5];
    const float* twist        = (const float*)d_in[6];
    const float* motion_noise = (const float*)d_in[7];
    const float* resample_u   = (const float*)d_in[8];
    const float* noise_after  = (const float*)d_in[9];
    float* out = (float*)d_out;

    // Dynamic smem: padded bitmap window + per-ray values + partials
    const int smemA = WIN_U32 * 4 + PPB * 128 * 4 + PPB * 4 * 4;   // ~65.5 KB
    cudaFuncSetAttribute(kernA, cudaFuncAttributeMaxDynamicSharedMemorySize, smemA);

    kernSetup<<<(WT * 8) / 256 + 1, 256>>>(map_grid, obs_angles);
    kernA<<<GRID, TPB, smemA>>>(particles, log_weights, obs_angles, obs_dists,
                                map_grid, sensor_table, twist, motion_noise);
    kernB1<<<1, 1024>>>(out);
    kernB2<<<NP / 256, 256>>>(noise_after, resample_u, out);
}